// round 8
// baseline (speedup 1.0000x reference)
#include <cuda_runtime.h>
#include <cuda_bf16.h>
#include <cstdint>

// ============================================================================
// GAT layer, N=4096, F=128, HEADS=8, U=8 -> out [4096, 64] fp32
// Collapsed to: Y[4096,80] = A @ X, where
//   X cols 0..63 : exp(e_r[h,j]) * HW[h,j,u]   (c = h*8+u)
//   X cols 64..71: exp(e_r[h,j])
//   X col  72    : 1.0 (degree)
//   X cols 73..79: 0 pad
// out[n, h*8+u] = elu( e^{e_l}*Y[n,c] / (e^{e_l}*Y[n,64+h] + N - Y[n,72]) )
// ============================================================================

#define NN 4096
#define FF 128
#define NB 80
#define MTILE 128
#define NSPLIT 4
#define KCHUNK 1024
#define NSTEPS 16      // KCHUNK / 64

// scratch (static device globals; no allocation allowed)
__device__ __align__(16) __nv_bfloat16 g_Xt_hi[NB * NN];
__device__ __align__(16) __nv_bfloat16 g_Xt_lo[NB * NN];
__device__ __align__(16) float g_el[8 * NN];
__device__ __align__(16) float g_part[NSPLIT * NN * NB];

__device__ __forceinline__ uint32_t smem_to_u32(const void* p) {
    uint32_t a;
    asm("{ .reg .u64 t; cvta.to.shared.u64 t, %1; cvt.u32.u64 %0, t; }"
        : "=r"(a) : "l"(p));
    return a;
}

// pack two fp32 -> bf16x2 (lo float in low half)
__device__ __forceinline__ uint32_t pack_bf16(float lo, float hi) {
    uint32_t r;
    asm("cvt.rn.bf16x2.f32 %0, %1, %2;" : "=r"(r) : "f"(hi), "f"(lo));
    return r;
}

__device__ __forceinline__ void lds32(uint32_t& v, uint32_t addr) {
    asm volatile("ld.shared.b32 %0, [%1];" : "=r"(v) : "r"(addr));
}

__device__ __forceinline__ void mma16816(float* d, const uint32_t* a,
                                         const uint32_t* b) {
    asm volatile(
        "mma.sync.aligned.m16n8k16.row.col.f32.bf16.bf16.f32 "
        "{%0,%1,%2,%3}, {%4,%5,%6,%7}, {%8,%9}, {%0,%1,%2,%3};"
        : "+f"(d[0]), "+f"(d[1]), "+f"(d[2]), "+f"(d[3])
        : "r"(a[0]), "r"(a[1]), "r"(a[2]), "r"(a[3]), "r"(b[0]), "r"(b[1]));
}

// ============================================================================
// K1: build X^T (bf16 hi/lo) and e_l. One block = 16 nodes, 256 threads.
// ============================================================================
__global__ __launch_bounds__(256) void k1_build(
    const float* __restrict__ H, const float* __restrict__ W,
    const float* __restrict__ aL, const float* __restrict__ aR)
{
    __shared__ float Hs[16 * 132];
    __shared__ float Ws[8 * 1028];
    __shared__ float aLs[64], aRs[64];

    const int tid = threadIdx.x;
    const int n0 = blockIdx.x * 16;

    for (int i = tid; i < 16 * 128; i += 256) {
        int nd = i >> 7, f = i & 127;
        Hs[nd * 132 + f] = H[(n0 + nd) * FF + f];
    }
    for (int i = tid; i < 8192; i += 256) {
        int h = i >> 10, rem = i & 1023;
        Ws[h * 1028 + rem] = W[i];
    }
    if (tid < 64) { aLs[tid] = aL[tid]; aRs[tid] = aR[tid]; }
    __syncthreads();

    const int node = tid >> 4;
    const int h    = (tid >> 1) & 7;
    const int half = tid & 1;
    const int u0   = half * 4;

    float a0 = 0.f, a1 = 0.f, a2 = 0.f, a3 = 0.f;
    const float* wp = &Ws[h * 1028 + u0];
    const float* hp = &Hs[node * 132];
#pragma unroll 8
    for (int f = 0; f < 128; f++) {
        float hv = hp[f];
        float4 w = *reinterpret_cast<const float4*>(wp + f * 8);
        a0 += hv * w.x; a1 += hv * w.y; a2 += hv * w.z; a3 += hv * w.w;
    }

    const float* arp = &aRs[h * 8 + u0];
    const float* alp = &aLs[h * 8 + u0];
    float er = a0 * arp[0] + a1 * arp[1] + a2 * arp[2] + a3 * arp[3];
    float el = a0 * alp[0] + a1 * alp[1] + a2 * alp[2] + a3 * alp[3];
    er += __shfl_xor_sync(0xFFFFFFFFu, er, 1);
    el += __shfl_xor_sync(0xFFFFFFFFu, el, 1);

    const float eer = expf(er);
    const int j = n0 + node;

    float vals[4] = { eer * a0, eer * a1, eer * a2, eer * a3 };
#pragma unroll
    for (int i = 0; i < 4; i++) {
        int c = h * 8 + u0 + i;
        float x = vals[i];
        __nv_bfloat16 hi = __float2bfloat16(x);
        g_Xt_hi[c * NN + j] = hi;
        g_Xt_lo[c * NN + j] = __float2bfloat16(x - __bfloat162float(hi));
    }
    if (half == 0) {
        int c = 64 + h;
        __nv_bfloat16 hi = __float2bfloat16(eer);
        g_Xt_hi[c * NN + j] = hi;
        g_Xt_lo[c * NN + j] = __float2bfloat16(eer - __bfloat162float(hi));
        g_el[h * NN + j] = el;
        if (h == 0) {
            g_Xt_hi[72 * NN + j] = __float2bfloat16(1.0f);
            g_Xt_lo[72 * NN + j] = __float2bfloat16(0.0f);
#pragma unroll
            for (int c2 = 73; c2 < 80; c2++) {
                g_Xt_hi[c2 * NN + j] = __float2bfloat16(0.0f);
                g_Xt_lo[c2 * NN + j] = __float2bfloat16(0.0f);
            }
        }
    }
}

// ============================================================================
// K2: HMMA bf16 GEMM partials. grid (32 m-tiles, 4 k-splits), 256 threads.
// SMEM (dynamic): A 2x(128x144B)=36864, Bhi 2x(80x144B)=23040, Blo same.
// Padded 144B row stride -> conflict-free b32 fragment loads.
// ============================================================================
#define ASTRIDE 144
#define BSTRIDE 144
#define SM_A  0
#define SM_BH 36864
#define SM_BL 59904
#define SMEM_K2 82944

__global__ __launch_bounds__(256, 1) void k2_gemm(const float* __restrict__ A)
{
    extern __shared__ char smem[];
    const uint32_t sb = smem_to_u32(smem);
    const int tid = threadIdx.x;
    const int wid = tid >> 5, lane = tid & 31;
    const int gid = lane >> 2, tg = lane & 3;
    const int m0 = blockIdx.x * MTILE;
    const int k0 = blockIdx.y * KCHUNK;
    const int mw = (wid >> 1) * 32;   // warp M offset within tile
    const int nw = (wid & 1) * 40;    // warp N offset

    float acc[2][5][4];
#pragma unroll
    for (int mi = 0; mi < 2; mi++)
#pragma unroll
        for (int ni = 0; ni < 5; ni++)
#pragma unroll
            for (int r = 0; r < 4; r++) acc[mi][ni][r] = 0.f;

    float4 aR[8];
    uint4  bR[5];

    // register-stage global loads for step s
    auto LOADG = [&](int s) {
        const float* Ab = A + (size_t)m0 * NN + k0 + s * 64;
#pragma unroll
        for (int t = 0; t < 8; t++) {
            int ch = tid + t * 256, row = ch >> 4, c = ch & 15;
            aR[t] = *reinterpret_cast<const float4*>(Ab + (size_t)row * NN + c * 4);
        }
#pragma unroll
        for (int t = 0; t < 5; t++) {
            int ch = tid + t * 256;
            int hl = ch >= 640;
            int rem = hl ? ch - 640 : ch;
            int r = rem >> 3, c = rem & 7;
            const __nv_bfloat16* src =
                (hl ? g_Xt_lo : g_Xt_hi) + (size_t)r * NN + k0 + s * 64;
            bR[t] = *(reinterpret_cast<const uint4*>(src) + c);
        }
    };
    auto STORE = [&](int buf) {
        uint32_t a_s = sb + SM_A + buf * 18432;
#pragma unroll
        for (int t = 0; t < 8; t++) {
            int ch = tid + t * 256, row = ch >> 4, c = ch & 15;
            uint32_t p0 = pack_bf16(aR[t].x, aR[t].y);
            uint32_t p1 = pack_bf16(aR[t].z, aR[t].w);
            uint32_t dst = a_s + row * ASTRIDE + c * 8;
            asm volatile("st.shared.v2.b32 [%0], {%1, %2};"
                         :: "r"(dst), "r"(p0), "r"(p1));
        }
#pragma unroll
        for (int t = 0; t < 5; t++) {
            int ch = tid + t * 256;
            int hl = ch >= 640;
            int rem = hl ? ch - 640 : ch;
            int r = rem >> 3, c = rem & 7;
            uint32_t bb = (hl ? sb + SM_BL : sb + SM_BH) + buf * 11520;
            uint32_t dst = bb + r * BSTRIDE + c * 16;
            asm volatile("st.shared.v4.b32 [%0], {%1, %2, %3, %4};"
                         :: "r"(dst), "r"(bR[t].x), "r"(bR[t].y),
                            "r"(bR[t].z), "r"(bR[t].w));
        }
    };

    LOADG(0);
    STORE(0);
    __syncthreads();

    for (int s = 0; s < NSTEPS; s++) {
        const int buf = s & 1;
        if (s + 1 < NSTEPS) LOADG(s + 1);   // overlap with MMA below

        const uint32_t a_s  = sb + SM_A  + buf * 18432;
        const uint32_t bh_s = sb + SM_BH + buf * 11520;
        const uint32_t bl_s = sb + SM_BL + buf * 11520;

#pragma unroll
        for (int t = 0; t < 4; t++) {
            uint32_t afr[2][4];
#pragma unroll
            for (int mi = 0; mi < 2; mi++) {
                uint32_t base = a_s + (mw + mi * 16 + gid) * ASTRIDE + t * 32 + tg * 4;
                lds32(afr[mi][0], base);
                lds32(afr[mi][1], base + 8 * ASTRIDE);
                lds32(afr[mi][2], base + 16);
                lds32(afr[mi][3], base + 8 * ASTRIDE + 16);
            }
#pragma unroll
            for (int ni = 0; ni < 5; ni++) {
                uint32_t b[2];
                uint32_t bb = bh_s + (nw + ni * 8 + gid) * BSTRIDE + t * 32 + tg * 4;
                lds32(b[0], bb);
                lds32(b[1], bb + 16);
                mma16816(acc[0][ni], afr[0], b);
                mma16816(acc[1][ni], afr[1], b);
            }
#pragma unroll
            for (int ni = 0; ni < 5; ni++) {
                uint32_t b[2];
                uint32_t bb = bl_s + (nw + ni * 8 + gid) * BSTRIDE + t * 32 + tg * 4;
                lds32(b[0], bb);
                lds32(b[1], bb + 16);
                mma16816(acc[0][ni], afr[0], b);
                mma16816(acc[1][ni], afr[1], b);
            }
        }
        __syncthreads();                       // everyone done reading buf
        if (s + 1 < NSTEPS) {
            STORE((s + 1) & 1);
            __syncthreads();
        }
    }

    // epilogue: write partials
    float* base = g_part + (size_t)blockIdx.y * NN * NB;
#pragma unroll
    for (int mi = 0; mi < 2; mi++) {
        int row0 = m0 + mw + mi * 16 + gid;
#pragma unroll
        for (int ni = 0; ni < 5; ni++) {
            int col = nw + ni * 8 + tg * 2;
            *reinterpret_cast<float2*>(base + (size_t)row0 * NB + col) =
                make_float2(acc[mi][ni][0], acc[mi][ni][1]);
            *reinterpret_cast<float2*>(base + (size_t)(row0 + 8) * NB + col) =
                make_float2(acc[mi][ni][2], acc[mi][ni][3]);
        }
    }
}

// ============================================================================
// K3: split-K reduce + GAT epilogue. 4096*64 outputs, 256 threads/block.
// ============================================================================
__global__ __launch_bounds__(256) void k3_epi(float* __restrict__ out)
{
    const int idx = blockIdx.x * 256 + threadIdx.x;
    const int n = idx >> 6, c = idx & 63;
    const int h = c >> 3;

    float y = 0.f, s = 0.f, d = 0.f;
#pragma unroll
    for (int sp = 0; sp < NSPLIT; sp++) {
        const float* p = g_part + ((size_t)sp * NN + n) * NB;
        y += p[c];
        s += p[64 + h];
        d += p[72];
    }
    const float eel = expf(g_el[h * NN + n]);
    const float denom = eel * s + ((float)NN - d);
    const float v = eel * y / denom;
    out[n * 64 + c] = (v > 0.f) ? v : expm1f(v);
}

// ============================================================================
extern "C" void kernel_launch(void* const* d_in, const int* in_sizes, int n_in,
                              void* d_out, int out_size)
{
    const float* A  = (const float*)d_in[0];
    const float* H  = (const float*)d_in[1];
    const float* W  = (const float*)d_in[2];
    const float* aL = (const float*)d_in[3];
    const float* aR = (const float*)d_in[4];
    float* out = (float*)d_out;

    cudaFuncSetAttribute(k2_gemm, cudaFuncAttributeMaxDynamicSharedMemorySize,
                         SMEM_K2);

    k1_build<<<NN / 16, 256>>>(H, W, aL, aR);
    k2_gemm<<<dim3(NN / MTILE, NSPLIT), 256, SMEM_K2>>>(A);
    k3_epi<<<NN * 64 / 256, 256>>>(out);
}

// round 9
// speedup vs baseline: 1.2173x; 1.2173x over previous
#include <cuda_runtime.h>
#include <cuda_bf16.h>
#include <cstdint>

// ============================================================================
// GAT layer, N=4096, F=128, HEADS=8, U=8 -> out [4096, 64] fp32
// Collapsed to: Y[4096,80] = A @ X, where
//   X cols 0..63 : exp(e_r[h,j]) * HW[h,j,u]   (c = h*8+u)
//   X cols 64..71: exp(e_r[h,j])
//   X col  72    : 1.0 (degree)
//   X cols 73..79: 0 pad
// out[n, h*8+u] = elu( e^{e_l}*Y[n,c] / (e^{e_l}*Y[n,64+h] + N - Y[n,72]) )
// ============================================================================

#define NN 4096
#define FF 128
#define NB 80
#define MTILE 128
#define NSPLIT 4
#define KCHUNK 1024
#define NSTEPS 16      // KCHUNK / 64

// scratch (static device globals; no allocation allowed)
__device__ __align__(16) __nv_bfloat16 g_Xt_hi[NB * NN];
__device__ __align__(16) __nv_bfloat16 g_Xt_lo[NB * NN];
__device__ __align__(16) float g_el[8 * NN];
__device__ __align__(16) float g_part[NSPLIT * NN * NB];

__device__ __forceinline__ uint32_t smem_to_u32(const void* p) {
    uint32_t a;
    asm("{ .reg .u64 t; cvta.to.shared.u64 t, %1; cvt.u32.u64 %0, t; }"
        : "=r"(a) : "l"(p));
    return a;
}

// pack two fp32 -> bf16x2 (lo float in low half)
__device__ __forceinline__ uint32_t pack_bf16(float lo, float hi) {
    uint32_t r;
    asm("cvt.rn.bf16x2.f32 %0, %1, %2;" : "=r"(r) : "f"(hi), "f"(lo));
    return r;
}

__device__ __forceinline__ void lds32(uint32_t& v, uint32_t addr) {
    asm volatile("ld.shared.b32 %0, [%1];" : "=r"(v) : "r"(addr));
}

__device__ __forceinline__ void mma16816(float* d, const uint32_t* a,
                                         const uint32_t* b) {
    asm volatile(
        "mma.sync.aligned.m16n8k16.row.col.f32.bf16.bf16.f32 "
        "{%0,%1,%2,%3}, {%4,%5,%6,%7}, {%8,%9}, {%0,%1,%2,%3};"
        : "+f"(d[0]), "+f"(d[1]), "+f"(d[2]), "+f"(d[3])
        : "r"(a[0]), "r"(a[1]), "r"(a[2]), "r"(a[3]), "r"(b[0]), "r"(b[1]));
}

// ============================================================================
// K1 (rewritten): build X^T (bf16 hi/lo) and e_l.
// 128 blocks x 128 threads; block = 32 nodes; thread = (h, half, slot) with
// 4 nodes per thread. Conflict-free smem mapping; coalesced staged stores.
// Dynamic smem layout:
//   [0]      Hs: 32 x 132 fp32 (16896 B)   -- aliased by sXt after compute
//   [16896]  Ws: 8 x 1028 fp32 (32896 B)
//   [49792]  aLs: 64 fp32 ; [50048] aRs: 64 fp32
// sXt alias region: sXth [80][32] bf16 (5120 B at 0), sXtl at 5120.
// ============================================================================
#define K1_HS   0
#define K1_WS   16896
#define K1_AL   49792
#define K1_AR   50048
#define K1_SMEM 50304
#define K1_XH   0
#define K1_XL   5120

__global__ __launch_bounds__(128, 1) void k1_build(
    const float* __restrict__ H, const float* __restrict__ W,
    const float* __restrict__ aL, const float* __restrict__ aR)
{
    extern __shared__ char smraw[];
    float* Hs  = reinterpret_cast<float*>(smraw + K1_HS);
    float* Ws  = reinterpret_cast<float*>(smraw + K1_WS);
    float* aLs = reinterpret_cast<float*>(smraw + K1_AL);
    float* aRs = reinterpret_cast<float*>(smraw + K1_AR);
    __nv_bfloat16* sXth = reinterpret_cast<__nv_bfloat16*>(smraw + K1_XH);
    __nv_bfloat16* sXtl = reinterpret_cast<__nv_bfloat16*>(smraw + K1_XL);

    const int tid = threadIdx.x;
    const int n0 = blockIdx.x * 32;

    // ---- fill Hs (32 nodes x 128, stride 132) ----
#pragma unroll
    for (int t = 0; t < 8; t++) {
        int i = tid + t * 128;                 // 0..1023 float4s
        int nd = i >> 5, f4 = i & 31;          // f4*4 = f
        float4 v = *reinterpret_cast<const float4*>(H + (size_t)(n0 + nd) * FF + f4 * 4);
        *reinterpret_cast<float4*>(&Hs[nd * 132 + f4 * 4]) = v;
    }
    // ---- fill Ws (8 heads x 1024, stride 1028) ----
#pragma unroll
    for (int t = 0; t < 16; t++) {
        int i = tid + t * 128;                 // 0..2047 float4s
        int h = i >> 8, r = (i & 255) * 4;
        float4 v = *reinterpret_cast<const float4*>(W + h * 1024 + r);
        *reinterpret_cast<float4*>(&Ws[h * 1028 + r]) = v;
    }
    if (tid < 64) { aLs[tid] = aL[tid]; aRs[tid] = aR[tid]; }
    __syncthreads();

    const int h    = tid & 7;
    const int half = (tid >> 3) & 1;
    const int slot = tid >> 4;                 // 0..7 -> nodes slot*4 .. +3
    const int u0   = half * 4;

    float acc[4][4];
#pragma unroll
    for (int p = 0; p < 4; p++)
#pragma unroll
        for (int u = 0; u < 4; u++) acc[p][u] = 0.f;

    const float* wp = &Ws[h * 1028 + u0];
    const float* hp = &Hs[slot * 4 * 132];

#pragma unroll 4
    for (int f = 0; f < 128; f++) {
        float4 w = *reinterpret_cast<const float4*>(wp + f * 8);
#pragma unroll
        for (int p = 0; p < 4; p++) {
            float hv = hp[p * 132 + f];
            acc[p][0] += hv * w.x; acc[p][1] += hv * w.y;
            acc[p][2] += hv * w.z; acc[p][3] += hv * w.w;
        }
    }

    const float* arp = &aRs[h * 8 + u0];
    const float* alp = &aLs[h * 8 + u0];
    float er[4], el[4], eer[4];
#pragma unroll
    for (int p = 0; p < 4; p++) {
        er[p] = acc[p][0]*arp[0] + acc[p][1]*arp[1] + acc[p][2]*arp[2] + acc[p][3]*arp[3];
        el[p] = acc[p][0]*alp[0] + acc[p][1]*alp[1] + acc[p][2]*alp[2] + acc[p][3]*alp[3];
        er[p] += __shfl_xor_sync(0xFFFFFFFFu, er[p], 8);
        el[p] += __shfl_xor_sync(0xFFFFFFFFu, el[p], 8);
        eer[p] = expf(er[p]);
    }

    __syncthreads();   // everyone done reading Hs; safe to alias with sXt

    // ---- stage Xt tile in smem: sXt[c][j_local], c=0..79, j_local=0..31 ----
#pragma unroll
    for (int p = 0; p < 4; p++) {
        int j = slot * 4 + p;
#pragma unroll
        for (int u = 0; u < 4; u++) {
            int c = h * 8 + u0 + u;
            float x = eer[p] * acc[p][u];
            __nv_bfloat16 hi = __float2bfloat16(x);
            sXth[c * 32 + j] = hi;
            sXtl[c * 32 + j] = __float2bfloat16(x - __bfloat162float(hi));
        }
        if (half == 0) {
            int c = 64 + h;
            __nv_bfloat16 hi = __float2bfloat16(eer[p]);
            sXth[c * 32 + j] = hi;
            sXtl[c * 32 + j] = __float2bfloat16(eer[p] - __bfloat162float(hi));
            g_el[h * NN + n0 + j] = el[p];
            if (h == 0) {
                sXth[72 * 32 + j] = __float2bfloat16(1.0f);
                sXtl[72 * 32 + j] = __float2bfloat16(0.0f);
#pragma unroll
                for (int c2 = 73; c2 < 80; c2++) {
                    sXth[c2 * 32 + j] = __float2bfloat16(0.0f);
                    sXtl[c2 * 32 + j] = __float2bfloat16(0.0f);
                }
            }
        }
    }
    __syncthreads();

    // ---- coalesced store: 80 rows x 64B (32 bf16) per buffer ----
    const uint4* srcH = reinterpret_cast<const uint4*>(sXth);
    const uint4* srcL = reinterpret_cast<const uint4*>(sXtl);
#pragma unroll
    for (int t = 0; t < 3; t++) {
        int i = tid + t * 128;                 // 0..319 uint4 chunks (80 rows * 4)
        if (i < 320) {
            int row = i >> 2, q = i & 3;
            *reinterpret_cast<uint4*>(g_Xt_hi + (size_t)row * NN + n0 + q * 8) = srcH[i];
            *reinterpret_cast<uint4*>(g_Xt_lo + (size_t)row * NN + n0 + q * 8) = srcL[i];
        }
    }
}

// ============================================================================
// K2: HMMA bf16 GEMM partials. grid (32 m-tiles, 4 k-splits), 256 threads.
// (unchanged from passing round)
// ============================================================================
#define ASTRIDE 144
#define BSTRIDE 144
#define SM_A  0
#define SM_BH 36864
#define SM_BL 59904
#define SMEM_K2 82944

__global__ __launch_bounds__(256, 1) void k2_gemm(const float* __restrict__ A)
{
    extern __shared__ char smem[];
    const uint32_t sb = smem_to_u32(smem);
    const int tid = threadIdx.x;
    const int wid = tid >> 5, lane = tid & 31;
    const int gid = lane >> 2, tg = lane & 3;
    const int m0 = blockIdx.x * MTILE;
    const int k0 = blockIdx.y * KCHUNK;
    const int mw = (wid >> 1) * 32;
    const int nw = (wid & 1) * 40;

    float acc[2][5][4];
#pragma unroll
    for (int mi = 0; mi < 2; mi++)
#pragma unroll
        for (int ni = 0; ni < 5; ni++)
#pragma unroll
            for (int r = 0; r < 4; r++) acc[mi][ni][r] = 0.f;

    float4 aR[8];
    uint4  bR[5];

    auto LOADG = [&](int s) {
        const float* Ab = A + (size_t)m0 * NN + k0 + s * 64;
#pragma unroll
        for (int t = 0; t < 8; t++) {
            int ch = tid + t * 256, row = ch >> 4, c = ch & 15;
            aR[t] = *reinterpret_cast<const float4*>(Ab + (size_t)row * NN + c * 4);
        }
#pragma unroll
        for (int t = 0; t < 5; t++) {
            int ch = tid + t * 256;
            int hl = ch >= 640;
            int rem = hl ? ch - 640 : ch;
            int r = rem >> 3, c = rem & 7;
            const __nv_bfloat16* src =
                (hl ? g_Xt_lo : g_Xt_hi) + (size_t)r * NN + k0 + s * 64;
            bR[t] = *(reinterpret_cast<const uint4*>(src) + c);
        }
    };
    auto STORE = [&](int buf) {
        uint32_t a_s = sb + SM_A + buf * 18432;
#pragma unroll
        for (int t = 0; t < 8; t++) {
            int ch = tid + t * 256, row = ch >> 4, c = ch & 15;
            uint32_t p0 = pack_bf16(aR[t].x, aR[t].y);
            uint32_t p1 = pack_bf16(aR[t].z, aR[t].w);
            uint32_t dst = a_s + row * ASTRIDE + c * 8;
            asm volatile("st.shared.v2.b32 [%0], {%1, %2};"
                         :: "r"(dst), "r"(p0), "r"(p1));
        }
#pragma unroll
        for (int t = 0; t < 5; t++) {
            int ch = tid + t * 256;
            int hl = ch >= 640;
            int rem = hl ? ch - 640 : ch;
            int r = rem >> 3, c = rem & 7;
            uint32_t bb = (hl ? sb + SM_BL : sb + SM_BH) + buf * 11520;
            uint32_t dst = bb + r * BSTRIDE + c * 16;
            asm volatile("st.shared.v4.b32 [%0], {%1, %2, %3, %4};"
                         :: "r"(dst), "r"(bR[t].x), "r"(bR[t].y),
                            "r"(bR[t].z), "r"(bR[t].w));
        }
    };

    LOADG(0);
    STORE(0);
    __syncthreads();

    for (int s = 0; s < NSTEPS; s++) {
        const int buf = s & 1;
        if (s + 1 < NSTEPS) LOADG(s + 1);

        const uint32_t a_s  = sb + SM_A  + buf * 18432;
        const uint32_t bh_s = sb + SM_BH + buf * 11520;
        const uint32_t bl_s = sb + SM_BL + buf * 11520;

#pragma unroll
        for (int t = 0; t < 4; t++) {
            uint32_t afr[2][4];
#pragma unroll
            for (int mi = 0; mi < 2; mi++) {
                uint32_t base = a_s + (mw + mi * 16 + gid) * ASTRIDE + t * 32 + tg * 4;
                lds32(afr[mi][0], base);
                lds32(afr[mi][1], base + 8 * ASTRIDE);
                lds32(afr[mi][2], base + 16);
                lds32(afr[mi][3], base + 8 * ASTRIDE + 16);
            }
#pragma unroll
            for (int ni = 0; ni < 5; ni++) {
                uint32_t b[2];
                uint32_t bb = bh_s + (nw + ni * 8 + gid) * BSTRIDE + t * 32 + tg * 4;
                lds32(b[0], bb);
                lds32(b[1], bb + 16);
                mma16816(acc[0][ni], afr[0], b);
                mma16816(acc[1][ni], afr[1], b);
            }
#pragma unroll
            for (int ni = 0; ni < 5; ni++) {
                uint32_t b[2];
                uint32_t bb = bl_s + (nw + ni * 8 + gid) * BSTRIDE + t * 32 + tg * 4;
                lds32(b[0], bb);
                lds32(b[1], bb + 16);
                mma16816(acc[0][ni], afr[0], b);
                mma16816(acc[1][ni], afr[1], b);
            }
        }
        __syncthreads();
        if (s + 1 < NSTEPS) {
            STORE((s + 1) & 1);
            __syncthreads();
        }
    }

    float* base = g_part + (size_t)blockIdx.y * NN * NB;
#pragma unroll
    for (int mi = 0; mi < 2; mi++) {
        int row0 = m0 + mw + mi * 16 + gid;
#pragma unroll
        for (int ni = 0; ni < 5; ni++) {
            int col = nw + ni * 8 + tg * 2;
            *reinterpret_cast<float2*>(base + (size_t)row0 * NB + col) =
                make_float2(acc[mi][ni][0], acc[mi][ni][1]);
            *reinterpret_cast<float2*>(base + (size_t)(row0 + 8) * NB + col) =
                make_float2(acc[mi][ni][2], acc[mi][ni][3]);
        }
    }
}

// ============================================================================
// K3: split-K reduce + GAT epilogue.
// ============================================================================
__global__ __launch_bounds__(256) void k3_epi(float* __restrict__ out)
{
    const int idx = blockIdx.x * 256 + threadIdx.x;
    const int n = idx >> 6, c = idx & 63;
    const int h = c >> 3;

    float y = 0.f, s = 0.f, d = 0.f;
#pragma unroll
    for (int sp = 0; sp < NSPLIT; sp++) {
        const float* p = g_part + ((size_t)sp * NN + n) * NB;
        y += p[c];
        s += p[64 + h];
        d += p[72];
    }
    const float eel = expf(g_el[h * NN + n]);
    const float denom = eel * s + ((float)NN - d);
    const float v = eel * y / denom;
    out[n * 64 + c] = (v > 0.f) ? v : expm1f(v);
}

// ============================================================================
extern "C" void kernel_launch(void* const* d_in, const int* in_sizes, int n_in,
                              void* d_out, int out_size)
{
    const float* A  = (const float*)d_in[0];
    const float* H  = (const float*)d_in[1];
    const float* W  = (const float*)d_in[2];
    const float* aL = (const float*)d_in[3];
    const float* aR = (const float*)d_in[4];
    float* out = (float*)d_out;

    cudaFuncSetAttribute(k1_build, cudaFuncAttributeMaxDynamicSharedMemorySize,
                         K1_SMEM);
    cudaFuncSetAttribute(k2_gemm, cudaFuncAttributeMaxDynamicSharedMemorySize,
                         SMEM_K2);

    k1_build<<<NN / 32, 128, K1_SMEM>>>(H, W, aL, aR);
    k2_gemm<<<dim3(NN / MTILE, NSPLIT), 256, SMEM_K2>>>(A);
    k3_epi<<<NN * 64 / 256, 256>>>(out);
}

// round 14
// speedup vs baseline: 1.2655x; 1.0396x over previous
#include <cuda_runtime.h>
#include <cuda_bf16.h>
#include <cstdint>

// ============================================================================
// GAT layer, N=4096, F=128, HEADS=8, U=8 -> out [4096, 64] fp32
// Collapsed to: Y[4096,80] = A @ X, where
//   X cols 0..63 : exp(e_r[h,j]) * HW[h,j,u]   (c = h*8+u)
//   X cols 64..71: exp(e_r[h,j])
//   X col  72    : 1.0 (degree)
//   X cols 73..79: 0 pad
// out[n, h*8+u] = elu( e^{e_l}*Y[n,c] / (e^{e_l}*Y[n,64+h] + N - Y[n,72]) )
// ============================================================================

#define NN 4096
#define FF 128
#define NB 80
#define MTILE 128
#define NSPLIT 4
#define KCHUNK 1024
#define NSTEPS 16      // KCHUNK / 64

// scratch (static device globals; no allocation allowed)
__device__ __align__(16) __nv_bfloat16 g_Xt_hi[NB * NN];
__device__ __align__(16) __nv_bfloat16 g_Xt_lo[NB * NN];
__device__ __align__(16) float g_el[8 * NN];
__device__ __align__(16) float g_part[NSPLIT * NN * NB];

__device__ __forceinline__ uint32_t smem_to_u32(const void* p) {
    uint32_t a;
    asm("{ .reg .u64 t; cvta.to.shared.u64 t, %1; cvt.u32.u64 %0, t; }"
        : "=r"(a) : "l"(p));
    return a;
}

// pack two fp32 -> bf16x2 (first arg in low half)
__device__ __forceinline__ uint32_t pack_bf16(float lo, float hi) {
    uint32_t r;
    asm("cvt.rn.bf16x2.f32 %0, %1, %2;" : "=r"(r) : "f"(hi), "f"(lo));
    return r;
}

__device__ __forceinline__ void lds32(uint32_t& v, uint32_t addr) {
    asm volatile("ld.shared.b32 %0, [%1];" : "=r"(v) : "r"(addr));
}

__device__ __forceinline__ void lds64f(float& a, float& b, uint32_t addr) {
    asm volatile("ld.shared.v2.f32 {%0, %1}, [%2];"
                 : "=f"(a), "=f"(b) : "r"(addr));
}

__device__ __forceinline__ void cp_async16(uint32_t dst, const void* src) {
    asm volatile("cp.async.cg.shared.global [%0], [%1], 16;"
                 :: "r"(dst), "l"(src) : "memory");
}
__device__ __forceinline__ void cp_commit() {
    asm volatile("cp.async.commit_group;" ::: "memory");
}
template <int N>
__device__ __forceinline__ void cp_wait() {
    asm volatile("cp.async.wait_group %0;" :: "n"(N) : "memory");
}

__device__ __forceinline__ void mma16816(float* d, const uint32_t* a,
                                         const uint32_t* b) {
    asm volatile(
        "mma.sync.aligned.m16n8k16.row.col.f32.bf16.bf16.f32 "
        "{%0,%1,%2,%3}, {%4,%5,%6,%7}, {%8,%9}, {%0,%1,%2,%3};"
        : "+f"(d[0]), "+f"(d[1]), "+f"(d[2]), "+f"(d[3])
        : "r"(a[0]), "r"(a[1]), "r"(a[2]), "r"(a[3]), "r"(b[0]), "r"(b[1]));
}

// ============================================================================
// K1: build X^T (bf16 hi/lo) and e_l.
// 128 blocks x 256 threads; block = 32 nodes; thread = (h, half, slot) with
// 2 nodes per thread (8 warps/SM for latency hiding).
// Dynamic smem:
//   [0]      Hs: 32 x 132 fp32 (16896 B)  -- aliased by sXt after compute
//   [16896]  Ws: 8 x 1028 fp32 (32896 B)
//   [49792]  aLs: 64 fp32 ; [50048] aRs: 64 fp32
// ============================================================================
#define K1_HS   0
#define K1_WS   16896
#define K1_AL   49792
#define K1_AR   50048
#define K1_SMEM 50304
#define K1_XH   0
#define K1_XL   5120

__global__ __launch_bounds__(256, 1) void k1_build(
    const float* __restrict__ H, const float* __restrict__ W,
    const float* __restrict__ aL, const float* __restrict__ aR)
{
    extern __shared__ char smraw[];
    float* Hs  = reinterpret_cast<float*>(smraw + K1_HS);
    float* Ws  = reinterpret_cast<float*>(smraw + K1_WS);
    float* aLs = reinterpret_cast<float*>(smraw + K1_AL);
    float* aRs = reinterpret_cast<float*>(smraw + K1_AR);
    __nv_bfloat16* sXth = reinterpret_cast<__nv_bfloat16*>(smraw + K1_XH);
    __nv_bfloat16* sXtl = reinterpret_cast<__nv_bfloat16*>(smraw + K1_XL);

    const int tid = threadIdx.x;
    const int n0 = blockIdx.x * 32;

    // ---- fill Hs (32 nodes x 128, stride 132) ----
#pragma unroll
    for (int t = 0; t < 4; t++) {
        int i = tid + t * 256;                 // 0..1023 float4s
        int nd = i >> 5, f4 = i & 31;
        float4 v = *reinterpret_cast<const float4*>(H + (size_t)(n0 + nd) * FF + f4 * 4);
        *reinterpret_cast<float4*>(&Hs[nd * 132 + f4 * 4]) = v;
    }
    // ---- fill Ws (8 heads x 1024, stride 1028) ----
#pragma unroll
    for (int t = 0; t < 8; t++) {
        int i = tid + t * 256;                 // 0..2047 float4s
        int h = i >> 8, r = (i & 255) * 4;
        float4 v = *reinterpret_cast<const float4*>(W + h * 1024 + r);
        *reinterpret_cast<float4*>(&Ws[h * 1028 + r]) = v;
    }
    if (tid < 64) { aLs[tid] = aL[tid]; aRs[tid] = aR[tid]; }
    __syncthreads();

    const int h    = tid & 7;
    const int half = (tid >> 3) & 1;
    const int slot = tid >> 4;                 // 0..15 -> nodes slot*2, slot*2+1
    const int u0   = half * 4;

    float acc[2][4];
#pragma unroll
    for (int p = 0; p < 2; p++)
#pragma unroll
        for (int u = 0; u < 4; u++) acc[p][u] = 0.f;

    const float* wp = &Ws[h * 1028 + u0];
    const float* hp = &Hs[slot * 2 * 132];

#pragma unroll 8
    for (int f = 0; f < 128; f++) {
        float4 w = *reinterpret_cast<const float4*>(wp + f * 8);
#pragma unroll
        for (int p = 0; p < 2; p++) {
            float hv = hp[p * 132 + f];
            acc[p][0] += hv * w.x; acc[p][1] += hv * w.y;
            acc[p][2] += hv * w.z; acc[p][3] += hv * w.w;
        }
    }

    const float* arp = &aRs[h * 8 + u0];
    const float* alp = &aLs[h * 8 + u0];
    float el[2], eer[2];
#pragma unroll
    for (int p = 0; p < 2; p++) {
        float er = acc[p][0]*arp[0] + acc[p][1]*arp[1] + acc[p][2]*arp[2] + acc[p][3]*arp[3];
        el[p]    = acc[p][0]*alp[0] + acc[p][1]*alp[1] + acc[p][2]*alp[2] + acc[p][3]*alp[3];
        er    += __shfl_xor_sync(0xFFFFFFFFu, er, 8);
        el[p] += __shfl_xor_sync(0xFFFFFFFFu, el[p], 8);
        eer[p] = expf(er);
    }

    __syncthreads();   // done reading Hs; safe to alias with sXt

    // ---- stage Xt tile: sXt[c][j_local], c=0..79, j_local=0..31 ----
#pragma unroll
    for (int p = 0; p < 2; p++) {
        int j = slot * 2 + p;
#pragma unroll
        for (int u = 0; u < 4; u++) {
            int c = h * 8 + u0 + u;
            float x = eer[p] * acc[p][u];
            __nv_bfloat16 hi = __float2bfloat16(x);
            sXth[c * 32 + j] = hi;
            sXtl[c * 32 + j] = __float2bfloat16(x - __bfloat162float(hi));
        }
        if (half == 0) {
            int c = 64 + h;
            __nv_bfloat16 hi = __float2bfloat16(eer[p]);
            sXth[c * 32 + j] = hi;
            sXtl[c * 32 + j] = __float2bfloat16(eer[p] - __bfloat162float(hi));
            g_el[h * NN + n0 + j] = el[p];
            if (h == 0) {
                sXth[72 * 32 + j] = __float2bfloat16(1.0f);
                sXtl[72 * 32 + j] = __float2bfloat16(0.0f);
#pragma unroll
                for (int c2 = 73; c2 < 80; c2++) {
                    sXth[c2 * 32 + j] = __float2bfloat16(0.0f);
                    sXtl[c2 * 32 + j] = __float2bfloat16(0.0f);
                }
            }
        }
    }
    __syncthreads();

    // ---- coalesced store: 320 uint4 chunks (80 rows x 4) per buffer ----
    const uint4* srcH = reinterpret_cast<const uint4*>(sXth);
    const uint4* srcL = reinterpret_cast<const uint4*>(sXtl);
#pragma unroll
    for (int t = 0; t < 2; t++) {
        int i = tid + t * 256;
        if (i < 320) {
            int row = i >> 2, q = i & 3;
            *reinterpret_cast<uint4*>(g_Xt_hi + (size_t)row * NN + n0 + q * 8) = srcH[i];
            *reinterpret_cast<uint4*>(g_Xt_lo + (size_t)row * NN + n0 + q * 8) = srcL[i];
        }
    }
}

// ============================================================================
// K2: HMMA bf16 GEMM partials, cp.async 3-stage pipeline.
// grid (32 m-tiles, 4 k-splits), 256 threads, 1 sync per K-step.
// Stage layout (59904 B):
//   [0]      A fp32: 128 rows x 288 B (64 floats + 32 B pad) = 36864
//   [36864]  B bf16: 160 rows x 144 B (rows 0..79 = hi, 80..159 = lo) = 23040
// ============================================================================
#define K2_ASTRIDE 288
#define K2_BSTRIDE 144
#define K2_ASZ     36864
#define K2_STAGE   59904
#define SMEM_K2    179712   // 3 stages

__global__ __launch_bounds__(256, 1) void k2_gemm(const float* __restrict__ A)
{
    extern __shared__ char smem[];
    const uint32_t sb = smem_to_u32(smem);
    const int tid = threadIdx.x;
    const int wid = tid >> 5, lane = tid & 31;
    const int gid = lane >> 2, tg = lane & 3;
    const int m0 = blockIdx.x * MTILE;
    const int k0 = blockIdx.y * KCHUNK;
    const int mw = (wid >> 1) * 32;   // warp M offset
    const int nw = (wid & 1) * 40;    // warp N offset

    float acc[2][5][4];
#pragma unroll
    for (int mi = 0; mi < 2; mi++)
#pragma unroll
        for (int ni = 0; ni < 5; ni++)
#pragma unroll
            for (int r = 0; r < 4; r++) acc[mi][ni][r] = 0.f;

    // issue all cp.async for stage s into buffer s%3
    auto LOAD_STAGE = [&](int s) {
        const uint32_t st = sb + (s % 3) * K2_STAGE;
        const float* Ab = A + (size_t)m0 * NN + k0 + s * 64;
        // A: 2048 x 16B chunks
#pragma unroll
        for (int t = 0; t < 8; t++) {
            int ch = tid + t * 256, row = ch >> 4, c = ch & 15;
            cp_async16(st + row * K2_ASTRIDE + c * 16,
                       Ab + (size_t)row * NN + c * 4);
        }
        // B: 1280 x 16B chunks (hi rows 0..79, lo rows 80..159)
#pragma unroll
        for (int t = 0; t < 5; t++) {
            int ch = tid + t * 256, row = ch >> 3, c = ch & 7;
            const __nv_bfloat16* src =
                (row < 80 ? g_Xt_hi + (size_t)row * NN
                          : g_Xt_lo + (size_t)(row - 80) * NN)
                + k0 + s * 64 + c * 8;
            cp_async16(st + K2_ASZ + row * K2_BSTRIDE + c * 16, src);
        }
    };

    LOAD_STAGE(0); cp_commit();
    LOAD_STAGE(1); cp_commit();

    for (int s = 0; s < NSTEPS; s++) {
        cp_wait<1>();          // stage s (group g_s) complete for this thread
        __syncthreads();       // visible to all; prev compute finished

        if (s + 2 < NSTEPS) LOAD_STAGE(s + 2);
        cp_commit();           // always commit (possibly empty group)

        const uint32_t a_s = sb + (s % 3) * K2_STAGE;
        const uint32_t b_s = a_s + K2_ASZ;

#pragma unroll
        for (int t = 0; t < 4; t++) {
            uint32_t afr[2][4];
#pragma unroll
            for (int mi = 0; mi < 2; mi++) {
                uint32_t base = a_s + (mw + mi * 16 + gid) * K2_ASTRIDE
                                + t * 64 + tg * 8;
                float x0, x1, x2, x3, y0, y1, y2, y3;
                lds64f(x0, x1, base);
                lds64f(y0, y1, base + 8 * K2_ASTRIDE);
                lds64f(x2, x3, base + 32);
                lds64f(y2, y3, base + 8 * K2_ASTRIDE + 32);
                afr[mi][0] = pack_bf16(x0, x1);
                afr[mi][1] = pack_bf16(y0, y1);
                afr[mi][2] = pack_bf16(x2, x3);
                afr[mi][3] = pack_bf16(y2, y3);
            }
#pragma unroll
            for (int ni = 0; ni < 5; ni++) {   // hi
                uint32_t b[2];
                uint32_t bb = b_s + (nw + ni * 8 + gid) * K2_BSTRIDE
                              + t * 32 + tg * 4;
                lds32(b[0], bb);
                lds32(b[1], bb + 16);
                mma16816(acc[0][ni], afr[0], b);
                mma16816(acc[1][ni], afr[1], b);
            }
#pragma unroll
            for (int ni = 0; ni < 5; ni++) {   // lo
                uint32_t bb = b_s + (80 + nw + ni * 8 + gid) * K2_BSTRIDE
                              + t * 32 + tg * 4;
                uint32_t b[2];
                lds32(b[0], bb);
                lds32(b[1], bb + 16);
                mma16816(acc[0][ni], afr[0], b);
                mma16816(acc[1][ni], afr[1], b);
            }
        }
    }

    // epilogue: write partials
    float* base = g_part + (size_t)blockIdx.y * NN * NB;
#pragma unroll
    for (int mi = 0; mi < 2; mi++) {
        int row0 = m0 + mw + mi * 16 + gid;
#pragma unroll
        for (int ni = 0; ni < 5; ni++) {
            int col = nw + ni * 8 + tg * 2;
            *reinterpret_cast<float2*>(base + (size_t)row0 * NB + col) =
                make_float2(acc[mi][ni][0], acc[mi][ni][1]);
            *reinterpret_cast<float2*>(base + (size_t)(row0 + 8) * NB + col) =
                make_float2(acc[mi][ni][2], acc[mi][ni][3]);
        }
    }
}

// ============================================================================
// K3: split-K reduce + GAT epilogue.
// ============================================================================
__global__ __launch_bounds__(256) void k3_epi(float* __restrict__ out)
{
    const int idx = blockIdx.x * 256 + threadIdx.x;
    const int n = idx >> 6, c = idx & 63;
    const int h = c >> 3;

    float y = 0.f, s = 0.f, d = 0.f;
#pragma unroll
    for (int sp = 0; sp < NSPLIT; sp++) {
        const float* p = g_part + ((size_t)sp * NN + n) * NB;
        y += p[c];
        s += p[64 + h];
        d += p[72];
    }
    const float eel = expf(g_el[h * NN + n]);
    const float denom = eel * s + ((float)NN - d);
    const float v = eel * y / denom;
    out[n * 64 + c] = (v > 0.f) ? v : expm1f(v);
}

// ============================================================================
extern "C" void kernel_launch(void* const* d_in, const int* in_sizes, int n_in,
                              void* d_out, int out_size)
{
    const float* A  = (const float*)d_in[0];
    const float* H  = (const float*)d_in[1];
    const float* W  = (const float*)d_in[2];
    const float* aL = (const float*)d_in[3];
    const float* aR = (const float*)d_in[4];
    float* out = (float*)d_out;

    cudaFuncSetAttribute(k1_build, cudaFuncAttributeMaxDynamicSharedMemorySize,
                         K1_SMEM);
    cudaFuncSetAttribute(k2_gemm, cudaFuncAttributeMaxDynamicSharedMemorySize,
                         SMEM_K2);

    k1_build<<<NN / 32, 256, K1_SMEM>>>(H, W, aL, aR);
    k2_gemm<<<dim3(NN / MTILE, NSPLIT), 256, SMEM_K2>>>(A);
    k3_epi<<<NN * 64 / 256, 256>>>(out);
}